// round 16
// baseline (speedup 1.0000x reference)
#include <cuda_runtime.h>
#include <cuda_bf16.h>
#include <cstdint>
#include <math.h>

// ---------------- problem constants ----------------
#define BT    80
#define MAXN  13
#define M_DIM 1040
#define K_DIM 26400
#define N_DIM 1024
#define A_DIM 6
#define G_DIM 5

// ---------------- GEMM config ----------------
#define K_PAD  26432              // 413 * 64
#define M_PAD  1152               // 9 * 128
#define KC     64                 // K elems per chunk (128B rows)
#define NCHUNK (K_PAD / KC)       // 413
#define GMT    128                // m tile
#define GNT    128                // n tile
#define NSLOT  18                 // flat-range slots (x8 n-tiles = 144 CTAs)
#define STAGES 3

#define TILE_BYTES (128 * 128)           // 16KB per operand tile
#define OFF_AH 0
#define OFF_AL (1 * TILE_BYTES)
#define OFF_BH (2 * TILE_BYTES)
#define OFF_BL (3 * TILE_BYTES)
#define STAGE_BYTES (4 * TILE_BYTES)     // 64KB
#define SMEM_TOTAL (STAGES * STAGE_BYTES) // 196608, 1 CTA/SM

// X path: 2 float4 per thread -> 8 fp32 per thread
#define XBLOCKS ((M_DIM * (K_DIM / 8) + 255) / 256)   // 13407
#define WBLOCKS ((K_PAD / 64) * (N_DIM / 32))          // 13216

// fused head smem: 13 rows x 1024 + pooled 1024 = 14336 floats
#define HEAD_SMEM ((MAXN + 1) * N_DIM * 4)             // 57344 bytes

// ---------------- device scratch ----------------
__device__ __align__(128) __nv_bfloat16 g_Xh[(size_t)M_PAD * K_PAD];  // dense rows
__device__ __align__(128) __nv_bfloat16 g_Xl[(size_t)M_PAD * K_PAD];
__device__ __align__(128) __nv_bfloat16 g_Wh[(size_t)N_DIM * K_PAD];
__device__ __align__(128) __nv_bfloat16 g_Wl[(size_t)N_DIM * K_PAD];
__device__ float g_Part[144 * 2 * GMT * GNT];   // per-CTA partial segments
__device__ int   g_rowsrc[M_DIM];
__device__ int   g_rowbase[BT];
__device__ int   g_Mvalid;

// ---------------- helpers ----------------
__device__ __forceinline__ uint32_t smem_u32(const void* p) {
    uint32_t a;
    asm("{ .reg .u64 t; cvta.to.shared.u64 t, %1; cvt.u32.u64 %0, t; }" : "=r"(a) : "l"(p));
    return a;
}
__device__ __forceinline__ void cp_async16(uint32_t dst, const void* src) {
    asm volatile("cp.async.cg.shared.global [%0], [%1], 16;" :: "r"(dst), "l"(src));
}
#define CP_COMMIT() asm volatile("cp.async.commit_group;" ::: "memory")
#define CP_WAIT1()  asm volatile("cp.async.wait_group 1;" ::: "memory")

#define LDSM_X4(r0, r1, r2, r3, addr) \
    asm volatile("ldmatrix.sync.aligned.m8n8.x4.shared.b16 {%0,%1,%2,%3}, [%4];" \
        : "=r"(r0), "=r"(r1), "=r"(r2), "=r"(r3) : "r"(addr))

__device__ __forceinline__ void mma_bf16(float* c, const uint32_t* a, const uint32_t* b) {
    asm volatile(
        "mma.sync.aligned.m16n8k16.row.col.f32.bf16.bf16.f32 "
        "{%0,%1,%2,%3}, {%4,%5,%6,%7}, {%8,%9}, {%0,%1,%2,%3};"
        : "+f"(c[0]), "+f"(c[1]), "+f"(c[2]), "+f"(c[3])
        : "r"(a[0]), "r"(a[1]), "r"(a[2]), "r"(a[3]), "r"(b[0]), "r"(b[1]));
}

__device__ __forceinline__ uint32_t swz_addr(uint32_t tile_base, int row, int c) {
    return tile_base + (uint32_t)(row * 128) + (uint32_t)((c ^ (row & 7)) << 4);
}

// 128-row tile: 1024 chunks / 256 threads = 4 iters
__device__ __forceinline__ void fill_tile128(uint32_t smem_tile, const __nv_bfloat16* gbase,
                                             int row0, int k0, int tid) {
    const char* base = (const char*)gbase;
    #pragma unroll
    for (int i = 0; i < 4; i++) {
        int idx = tid + i * 256;
        int row = idx >> 3;
        int c   = idx & 7;
        const char* src = base + ((size_t)(row0 + row) * K_PAD + (size_t)k0) * 2 + c * 16;
        cp_async16(swz_addr(smem_tile, row, c), src);
    }
}
__device__ __forceinline__ void fill_stage(uint32_t st, int im, int bn, int j, int tid) {
    fill_tile128(st + OFF_AH, g_Xh, im * GMT, j * KC, tid);
    fill_tile128(st + OFF_AL, g_Xl, im * GMT, j * KC, tid);
    fill_tile128(st + OFF_BH, g_Wh, bn,       j * KC, tid);
    fill_tile128(st + OFF_BL, g_Wl, bn,       j * KC, tid);
}

// load all fragments for one kk step
__device__ __forceinline__ void load_frags(uint32_t st, int kk, int aRow0, int cA,
                                           int bRow0, int cB,
                                           uint32_t ah[2][4], uint32_t al[2][4],
                                           uint32_t bh[4][4], uint32_t bl[4][4]) {
    #pragma unroll
    for (int mi = 0; mi < 2; mi++) {
        LDSM_X4(ah[mi][0], ah[mi][1], ah[mi][2], ah[mi][3],
                swz_addr(st + OFF_AH, aRow0 + mi * 16, kk * 2 + cA));
        LDSM_X4(al[mi][0], al[mi][1], al[mi][2], al[mi][3],
                swz_addr(st + OFF_AL, aRow0 + mi * 16, kk * 2 + cA));
    }
    #pragma unroll
    for (int nb = 0; nb < 4; nb++) {
        LDSM_X4(bh[nb][0], bh[nb][1], bh[nb][2], bh[nb][3],
                swz_addr(st + OFF_BH, bRow0 + nb * 16, kk * 2 + cB));
        LDSM_X4(bl[nb][0], bl[nb][1], bl[nb][2], bl[nb][3],
                swz_addr(st + OFF_BL, bRow0 + nb * 16, kk * 2 + cB));
    }
}

// ---------------- Kernel: ragged prefix / row map ----------------
__global__ __launch_bounds__(128)
void prefix_kernel(const int* __restrict__ bboxes_num) {
    __shared__ int pre[BT];
    const int tid = threadIdx.x;
    if (tid == 0) {
        int acc = 0;
        #pragma unroll 1
        for (int i = 0; i < BT; i++) {
            pre[i] = acc;
            int nv = bboxes_num[i];
            nv = nv < 1 ? 1 : (nv > MAXN ? MAXN : nv);
            acc += nv;
        }
        g_Mvalid = acc;
    }
    __syncthreads();
    for (int i = tid; i < BT; i += 128) {
        int base = pre[i];
        g_rowbase[i] = base;
        int nv = bboxes_num[i];
        nv = nv < 1 ? 1 : (nv > MAXN ? MAXN : nv);
        for (int n = 0; n < nv; n++) g_rowsrc[base + n] = i * MAXN + n;
    }
}

// ---------------- Kernel: merged converts (X gather-split x2 | W transpose-split) ----------------
__global__ __launch_bounds__(256)
void convert_kernel(const float* __restrict__ X, const float* __restrict__ W) {
    __shared__ float s[64][33];
    const int bid = blockIdx.x;
    const int tid = threadIdx.x;

    if (bid < XBLOCKS) {
        // ---- X: 2 float4 per thread (8 fp32), gathered valid rows ----
        size_t t = (size_t)bid * 256 + tid;
        const size_t total = (size_t)M_DIM * (K_DIM / 8);
        if (t >= total) return;
        int d  = (int)(t / (K_DIM / 8));
        if (d >= g_Mvalid) return;
        int kk = (int)(t % (K_DIM / 8)) * 8;
        int src = g_rowsrc[d];
        const float* xp = X + (size_t)src * K_DIM + kk;
        float4 v0 = *(const float4*)(xp);
        float4 v1 = *(const float4*)(xp + 4);
        float f[8] = {v0.x, v0.y, v0.z, v0.w, v1.x, v1.y, v1.z, v1.w};
        uint32_t hi[4], lo[4];
        #pragma unroll
        for (int p = 0; p < 4; p++) {
            __nv_bfloat16 h0 = __float2bfloat16(f[2*p+0]);
            __nv_bfloat16 h1 = __float2bfloat16(f[2*p+1]);
            __nv_bfloat16 l0 = __float2bfloat16(f[2*p+0] - __bfloat162float(h0));
            __nv_bfloat16 l1 = __float2bfloat16(f[2*p+1] - __bfloat162float(h1));
            hi[p] = (uint32_t)__bfloat16_as_ushort(h0) | ((uint32_t)__bfloat16_as_ushort(h1) << 16);
            lo[p] = (uint32_t)__bfloat16_as_ushort(l0) | ((uint32_t)__bfloat16_as_ushort(l1) << 16);
        }
        size_t o = (size_t)d * K_PAD + kk;
        *(uint4*)(g_Xh + o) = make_uint4(hi[0], hi[1], hi[2], hi[3]);
        *(uint4*)(g_Xl + o) = make_uint4(lo[0], lo[1], lo[2], lo[3]);
    } else {
        // ---- W: transpose [K,N] -> [N,K_PAD] + split ----
        const int wb = bid - XBLOCKS;
        const int k0 = (wb % (K_PAD / 64)) * 64;
        const int n0 = (wb / (K_PAD / 64)) * 32;
        {
            int kr = tid >> 2;
            int nb = (tid & 3) * 8;
            int k = k0 + kr;
            if (k < K_DIM) {
                float4 a = *(const float4*)(W + (size_t)k * N_DIM + n0 + nb);
                float4 b = *(const float4*)(W + (size_t)k * N_DIM + n0 + nb + 4);
                s[kr][nb+0]=a.x; s[kr][nb+1]=a.y; s[kr][nb+2]=a.z; s[kr][nb+3]=a.w;
                s[kr][nb+4]=b.x; s[kr][nb+5]=b.y; s[kr][nb+6]=b.z; s[kr][nb+7]=b.w;
            } else {
                #pragma unroll
                for (int i = 0; i < 8; i++) s[kr][nb+i] = 0.0f;
            }
        }
        __syncthreads();
        {
            int nr = tid >> 3;
            int kb = (tid & 7) * 8;
            uint32_t hi[4], lo[4];
            #pragma unroll
            for (int p = 0; p < 4; p++) {
                float f0 = s[kb + 2*p + 0][nr];
                float f1 = s[kb + 2*p + 1][nr];
                __nv_bfloat16 h0 = __float2bfloat16(f0);
                __nv_bfloat16 h1 = __float2bfloat16(f1);
                __nv_bfloat16 l0 = __float2bfloat16(f0 - __bfloat162float(h0));
                __nv_bfloat16 l1 = __float2bfloat16(f1 - __bfloat162float(h1));
                hi[p] = (uint32_t)__bfloat16_as_ushort(h0) | ((uint32_t)__bfloat16_as_ushort(h1) << 16);
                lo[p] = (uint32_t)__bfloat16_as_ushort(l0) | ((uint32_t)__bfloat16_as_ushort(l1) << 16);
            }
            size_t o = (size_t)(n0 + nr) * K_PAD + k0 + kb;
            *(uint4*)(g_Wh + o) = make_uint4(hi[0], hi[1], hi[2], hi[3]);
            *(uint4*)(g_Wl + o) = make_uint4(lo[0], lo[1], lo[2], lo[3]);
        }
    }
}

// ---------------- Kernel: GEMM 128x128, warp 32x64, flat partition, frag double-buffer ----------------
__global__ void __launch_bounds__(256, 1)
gemm_kernel() {
    extern __shared__ char smem[];
    const uint32_t sb = smem_u32(smem);
    const int tid  = threadIdx.x;
    const int lane = tid & 31;
    const int wid  = tid >> 5;
    const int bid  = blockIdx.x;
    const int in   = bid & 7;
    const int slot = bid >> 3;
    const int bn   = in * GNT;

    const int mv     = g_Mvalid;
    const int tilesM = (mv + GMT - 1) / GMT;
    const int totalF = tilesM * NCHUNK;
    const int f0 = (slot * totalF) / NSLOT;
    const int f1 = ((slot + 1) * totalF) / NSLOT;

    const int m_off = (wid & 3) * 32;     // 4 warps down M
    const int n_off = (wid >> 2) * 64;    // 2 warps across N

    float acc[2][8][4];
    #pragma unroll
    for (int mi = 0; mi < 2; mi++)
        #pragma unroll
        for (int ni = 0; ni < 8; ni++)
            #pragma unroll
            for (int q = 0; q < 4; q++) acc[mi][ni][q] = 0.0f;

    const int aRow0 = m_off + (lane & 15);
    const int cA    = lane >> 4;
    const int bRow0 = n_off + ((lane & 16) >> 1) + (lane & 7);
    const int cB    = (lane >> 3) & 1;

    int im = f0 / NCHUNK;
    int j  = f0 - im * NCHUNK;

    fill_stage(sb + 0 * STAGE_BYTES, im, bn, j, tid);
    CP_COMMIT();
    if (f0 + 1 < f1) {
        int im1 = (f0 + 1) / NCHUNK;
        int j1  = (f0 + 1) - im1 * NCHUNK;
        fill_stage(sb + 1 * STAGE_BYTES, im1, bn, j1, tid);
    }
    CP_COMMIT();

    int seg = 0;
    for (int f = f0; f < f1; f++) {
        const int sidx = (f - f0) % STAGES;
        CP_WAIT1();
        __syncthreads();

        if (f + 2 < f1) {
            int imp = (f + 2) / NCHUNK;
            int jp  = (f + 2) - imp * NCHUNK;
            fill_stage(sb + ((f - f0 + 2) % STAGES) * STAGE_BYTES, imp, bn, jp, tid);
        }
        CP_COMMIT();

        const uint32_t st = sb + sidx * STAGE_BYTES;

        // double-buffered fragments across kk
        uint32_t ah[2][2][4], al[2][2][4], bh[2][4][4], bl[2][4][4];
        load_frags(st, 0, aRow0, cA, bRow0, cB, ah[0], al[0], bh[0], bl[0]);
        #pragma unroll
        for (int kk = 0; kk < 4; kk++) {
            const int cur = kk & 1;
            const int nxt = cur ^ 1;
            if (kk < 3)
                load_frags(st, kk + 1, aRow0, cA, bRow0, cB, ah[nxt], al[nxt], bh[nxt], bl[nxt]);
            #pragma unroll
            for (int mi = 0; mi < 2; mi++) {
                #pragma unroll
                for (int ni = 0; ni < 8; ni++) {
                    const uint32_t* fh = &bh[cur][ni >> 1][(ni & 1) * 2];
                    const uint32_t* fl = &bl[cur][ni >> 1][(ni & 1) * 2];
                    mma_bf16(acc[mi][ni], ah[cur][mi], fh);
                    mma_bf16(acc[mi][ni], ah[cur][mi], fl);
                    mma_bf16(acc[mi][ni], al[cur][mi], fh);
                }
            }
        }

        // advance / flush at m-tile boundary or range end
        j++;
        const bool bound = (j == NCHUNK);
        const bool last  = (f == f1 - 1);
        if (bound) j = 0;
        if (bound || last) {
            float* P = g_Part + ((size_t)bid * 2 + seg) * (GMT * GNT);
            #pragma unroll
            for (int mi = 0; mi < 2; mi++) {
                #pragma unroll
                for (int ni = 0; ni < 8; ni++) {
                    int r0 = m_off + mi * 16 + (lane >> 2);
                    int cc = n_off + ni * 8 + (lane & 3) * 2;
                    *(float2*)(P + r0 * GNT + cc) = make_float2(acc[mi][ni][0], acc[mi][ni][1]);
                    *(float2*)(P + (r0 + 8) * GNT + cc) = make_float2(acc[mi][ni][2], acc[mi][ni][3]);
                    #pragma unroll
                    for (int q = 0; q < 4; q++) acc[mi][ni][q] = 0.0f;
                }
            }
            seg++;
            if (bound) im++;
        }
    }
}

// ---------------- Kernel: fused reduce + head (one block per frame) ----------------
// Phase 1: gather this frame's valid rows from g_Part (+bias+ReLU) into smem.
// Phase 2: masked max-pool + activities + per-box action scores.
__global__ __launch_bounds__(256)
void head_kernel(const float* __restrict__ bias,
                 const float* __restrict__ w_act,
                 const float* __restrict__ b_act,
                 const float* __restrict__ w_acty,
                 const float* __restrict__ b_acty,
                 const int*   __restrict__ bboxes_num,
                 float* __restrict__ out) {
    extern __shared__ float hsm[];                 // [MAXN][1024] + pooled[1024]
    float* pooled = hsm + MAXN * N_DIM;
    const int bt   = blockIdx.x;
    const int tid  = threadIdx.x;
    const int lane = tid & 31;
    const int warp = tid >> 5;

    int nvalid = bboxes_num[bt];
    nvalid = nvalid < 1 ? 1 : (nvalid > MAXN ? MAXN : nvalid);
    const int base = g_rowbase[bt];
    const int mv   = g_Mvalid;
    const int tilesM = (mv + GMT - 1) / GMT;
    const int totalF = tilesM * NCHUNK;

    // ---- phase 1: reduce Part -> smem h rows (one f4 column per thread per row) ----
    const int c  = tid;                            // float4 col 0..255
    const int in = c >> 5;                         // n-tile
    const int lc = (c & 31) * 4;
    const float4 bi = *(const float4*)(bias + c * 4);

    #pragma unroll 1
    for (int n = 0; n < nvalid; n++) {
        const int d    = base + n;
        const int im   = d >> 7;
        const int rloc = d & 127;
        int sLo = (int)(((long)im * NCHUNK * NSLOT) / totalF) - 1;
        if (sLo < 0) sLo = 0;
        int sHi = (int)(((long)(im + 1) * NCHUNK * NSLOT) / totalF) + 2;
        if (sHi > NSLOT) sHi = NSLOT;

        float4 sum = bi;
        #pragma unroll 1
        for (int slot = sLo; slot < sHi; slot++) {
            int f0   = (slot * totalF) / NSLOT;
            int f1   = ((slot + 1) * totalF) / NSLOT;
            int imLo = f0 / NCHUNK;
            int imHi = (f1 - 1) / NCHUNK;
            int seg = -1;
            if (im == imLo) seg = 0;
            else if (im == imHi) seg = 1;
            if (seg >= 0) {
                const float* P = g_Part + (((size_t)(slot * 8 + in)) * 2 + seg) * (GMT * GNT);
                float4 v = *(const float4*)(P + rloc * GNT + lc);
                sum.x += v.x; sum.y += v.y; sum.z += v.z; sum.w += v.w;
            }
        }
        float4 h;
        h.x = fmaxf(sum.x, 0.0f); h.y = fmaxf(sum.y, 0.0f);
        h.z = fmaxf(sum.z, 0.0f); h.w = fmaxf(sum.w, 0.0f);
        *(float4*)(hsm + n * N_DIM + c * 4) = h;
    }

    // masked max-pool into pooled (n=0 always valid)
    {
        float4 m = *(const float4*)(hsm + c * 4);
        #pragma unroll 1
        for (int n = 1; n < nvalid; n++) {
            float4 v = *(const float4*)(hsm + n * N_DIM + c * 4);
            m.x = fmaxf(m.x, v.x); m.y = fmaxf(m.y, v.y);
            m.z = fmaxf(m.z, v.z); m.w = fmaxf(m.w, v.w);
        }
        *(float4*)(pooled + c * 4) = m;
    }
    __syncthreads();

    // ---- phase 2a: activities (5 warp dots over pooled) ----
    for (int g = warp; g < G_DIM; g += 8) {
        float s = 0.0f;
        #pragma unroll 4
        for (int i = lane; i < 256; i += 32) {
            float4 pv = *(const float4*)(pooled + i * 4);
            int f = i * 4;
            s = fmaf(pv.x, w_acty[(f + 0) * G_DIM + g], s);
            s = fmaf(pv.y, w_acty[(f + 1) * G_DIM + g], s);
            s = fmaf(pv.z, w_acty[(f + 2) * G_DIM + g], s);
            s = fmaf(pv.w, w_acty[(f + 3) * G_DIM + g], s);
        }
        #pragma unroll
        for (int o = 16; o; o >>= 1) s += __shfl_xor_sync(0xFFFFFFFFu, s, o);
        if (lane == 0)
            out[BT * MAXN * A_DIM + bt * G_DIM + g] = s + b_acty[g];
    }

    // ---- phase 2b: actions (78 warp dots; invalid boxes -> 0) ----
    const int total = nvalid * A_DIM;
    for (int p = warp; p < MAXN * A_DIM; p += 8) {
        int n = p / A_DIM;
        int a = p % A_DIM;
        if (p < total) {
            const float* hr = hsm + n * N_DIM;
            float s = 0.0f;
            #pragma unroll 4
            for (int i = lane; i < 256; i += 32) {
                float4 hv = *(const float4*)(hr + i * 4);
                int f = i * 4;
                s = fmaf(hv.x, w_act[(f + 0) * A_DIM + a], s);
                s = fmaf(hv.y, w_act[(f + 1) * A_DIM + a], s);
                s = fmaf(hv.z, w_act[(f + 2) * A_DIM + a], s);
                s = fmaf(hv.w, w_act[(f + 3) * A_DIM + a], s);
            }
            #pragma unroll
            for (int o = 16; o; o >>= 1) s += __shfl_xor_sync(0xFFFFFFFFu, s, o);
            if (lane == 0) out[(bt * MAXN + n) * A_DIM + a] = s + b_act[a];
        } else if (lane == 0) {
            out[(bt * MAXN + n) * A_DIM + a] = 0.0f;
        }
    }
}

// ---------------- launch ----------------
extern "C" void kernel_launch(void* const* d_in, const int* in_sizes, int n_in,
                              void* d_out, int out_size) {
    const float* X      = (const float*)d_in[0];
    const float* w_emb  = (const float*)d_in[1];
    const float* b_emb  = (const float*)d_in[2];
    const float* w_act  = (const float*)d_in[3];
    const float* b_act  = (const float*)d_in[4];
    const float* w_acty = (const float*)d_in[5];
    const float* b_acty = (const float*)d_in[6];
    const int*   bboxes = (const int*)d_in[7];
    float* out = (float*)d_out;

    cudaFuncSetAttribute(gemm_kernel, cudaFuncAttributeMaxDynamicSharedMemorySize, SMEM_TOTAL);
    cudaFuncSetAttribute(head_kernel, cudaFuncAttributeMaxDynamicSharedMemorySize, HEAD_SMEM);

    prefix_kernel<<<1, 128>>>(bboxes);
    convert_kernel<<<XBLOCKS + WBLOCKS, 256>>>(X, w_emb);
    gemm_kernel<<<8 * NSLOT, 256, SMEM_TOTAL>>>();       // 144 CTAs, flat-balanced
    head_kernel<<<BT, 256, HEAD_SMEM>>>(b_emb, w_act, b_act, w_acty, b_acty, bboxes, out);
}

// round 17
// speedup vs baseline: 1.1184x; 1.1184x over previous
#include <cuda_runtime.h>
#include <cuda_bf16.h>
#include <cstdint>
#include <math.h>

// ---------------- problem constants ----------------
#define BT    80
#define MAXN  13
#define M_DIM 1040
#define K_DIM 26400
#define N_DIM 1024
#define A_DIM 6
#define G_DIM 5

// ---------------- GEMM config ----------------
#define K_PAD  26432              // 413 * 64
#define M_PAD  1152               // 9 * 128
#define KC     64                 // K elems per chunk (128B rows)
#define NCHUNK (K_PAD / KC)       // 413
#define GMT    128                // m tile
#define GNT    128                // n tile
#define NSLOT  18                 // flat-range slots (x8 n-tiles = 144 CTAs)
#define STAGES 3

#define TILE_BYTES (128 * 128)           // 16KB per operand tile
#define OFF_AH 0
#define OFF_AL (1 * TILE_BYTES)
#define OFF_BH (2 * TILE_BYTES)
#define OFF_BL (3 * TILE_BYTES)
#define STAGE_BYTES (4 * TILE_BYTES)     // 64KB
#define SMEM_TOTAL (STAGES * STAGE_BYTES) // 196608, 1 CTA/SM

// X path: 2 float4 per thread -> 8 fp32 per thread
#define XBLOCKS ((M_DIM * (K_DIM / 8) + 255) / 256)   // 13407
#define WBLOCKS ((K_PAD / 64) * (N_DIM / 32))          // 13216

// ---------------- device scratch ----------------
__device__ __align__(128) __nv_bfloat16 g_Xh[(size_t)M_PAD * K_PAD];  // dense rows
__device__ __align__(128) __nv_bfloat16 g_Xl[(size_t)M_PAD * K_PAD];
__device__ __align__(128) __nv_bfloat16 g_Wh[(size_t)N_DIM * K_PAD];
__device__ __align__(128) __nv_bfloat16 g_Wl[(size_t)N_DIM * K_PAD];
__device__ float g_Part[144 * 2 * GMT * GNT];   // per-CTA partial segments
__device__ float g_H[(size_t)M_DIM * N_DIM];
__device__ int   g_rowsrc[M_DIM];
__device__ int   g_Mvalid;

// ---------------- helpers ----------------
__device__ __forceinline__ uint32_t smem_u32(const void* p) {
    uint32_t a;
    asm("{ .reg .u64 t; cvta.to.shared.u64 t, %1; cvt.u32.u64 %0, t; }" : "=r"(a) : "l"(p));
    return a;
}
__device__ __forceinline__ void cp_async16(uint32_t dst, const void* src) {
    asm volatile("cp.async.cg.shared.global [%0], [%1], 16;" :: "r"(dst), "l"(src));
}
#define CP_COMMIT() asm volatile("cp.async.commit_group;" ::: "memory")
#define CP_WAIT1()  asm volatile("cp.async.wait_group 1;" ::: "memory")

#define LDSM_X4(r0, r1, r2, r3, addr) \
    asm volatile("ldmatrix.sync.aligned.m8n8.x4.shared.b16 {%0,%1,%2,%3}, [%4];" \
        : "=r"(r0), "=r"(r1), "=r"(r2), "=r"(r3) : "r"(addr))

__device__ __forceinline__ void mma_bf16(float* c, const uint32_t* a, const uint32_t* b) {
    asm volatile(
        "mma.sync.aligned.m16n8k16.row.col.f32.bf16.bf16.f32 "
        "{%0,%1,%2,%3}, {%4,%5,%6,%7}, {%8,%9}, {%0,%1,%2,%3};"
        : "+f"(c[0]), "+f"(c[1]), "+f"(c[2]), "+f"(c[3])
        : "r"(a[0]), "r"(a[1]), "r"(a[2]), "r"(a[3]), "r"(b[0]), "r"(b[1]));
}

__device__ __forceinline__ uint32_t swz_addr(uint32_t tile_base, int row, int c) {
    return tile_base + (uint32_t)(row * 128) + (uint32_t)((c ^ (row & 7)) << 4);
}

// 128-row tile: 1024 chunks / 256 threads = 4 iters
__device__ __forceinline__ void fill_tile128(uint32_t smem_tile, const __nv_bfloat16* gbase,
                                             int row0, int k0, int tid) {
    const char* base = (const char*)gbase;
    #pragma unroll
    for (int i = 0; i < 4; i++) {
        int idx = tid + i * 256;
        int row = idx >> 3;
        int c   = idx & 7;
        const char* src = base + ((size_t)(row0 + row) * K_PAD + (size_t)k0) * 2 + c * 16;
        cp_async16(swz_addr(smem_tile, row, c), src);
    }
}
__device__ __forceinline__ void fill_stage(uint32_t st, int im, int bn, int j, int tid) {
    fill_tile128(st + OFF_AH, g_Xh, im * GMT, j * KC, tid);
    fill_tile128(st + OFF_AL, g_Xl, im * GMT, j * KC, tid);
    fill_tile128(st + OFF_BH, g_Wh, bn,       j * KC, tid);
    fill_tile128(st + OFF_BL, g_Wl, bn,       j * KC, tid);
}

// load all fragments for one kk step
__device__ __forceinline__ void load_frags(uint32_t st, int kk, int aRow0, int cA,
                                           int bRow0, int cB,
                                           uint32_t ah[2][4], uint32_t al[2][4],
                                           uint32_t bh[4][4], uint32_t bl[4][4]) {
    #pragma unroll
    for (int mi = 0; mi < 2; mi++) {
        LDSM_X4(ah[mi][0], ah[mi][1], ah[mi][2], ah[mi][3],
                swz_addr(st + OFF_AH, aRow0 + mi * 16, kk * 2 + cA));
        LDSM_X4(al[mi][0], al[mi][1], al[mi][2], al[mi][3],
                swz_addr(st + OFF_AL, aRow0 + mi * 16, kk * 2 + cA));
    }
    #pragma unroll
    for (int nb = 0; nb < 4; nb++) {
        LDSM_X4(bh[nb][0], bh[nb][1], bh[nb][2], bh[nb][3],
                swz_addr(st + OFF_BH, bRow0 + nb * 16, kk * 2 + cB));
        LDSM_X4(bl[nb][0], bl[nb][1], bl[nb][2], bl[nb][3],
                swz_addr(st + OFF_BL, bRow0 + nb * 16, kk * 2 + cB));
    }
}

// ---------------- Kernel: ragged prefix / row map ----------------
__global__ __launch_bounds__(128)
void prefix_kernel(const int* __restrict__ bboxes_num) {
    __shared__ int pre[BT];
    const int tid = threadIdx.x;
    if (tid == 0) {
        int acc = 0;
        #pragma unroll 1
        for (int i = 0; i < BT; i++) {
            pre[i] = acc;
            int nv = bboxes_num[i];
            nv = nv < 1 ? 1 : (nv > MAXN ? MAXN : nv);
            acc += nv;
        }
        g_Mvalid = acc;
    }
    __syncthreads();
    for (int i = tid; i < BT; i += 128) {
        int base = pre[i];
        int nv = bboxes_num[i];
        nv = nv < 1 ? 1 : (nv > MAXN ? MAXN : nv);
        for (int n = 0; n < nv; n++) g_rowsrc[base + n] = i * MAXN + n;
    }
}

// ---------------- Kernel: merged converts (X gather-split x2 | W transpose-split) ----------------
__global__ __launch_bounds__(256)
void convert_kernel(const float* __restrict__ X, const float* __restrict__ W) {
    __shared__ float s[64][33];
    const int bid = blockIdx.x;
    const int tid = threadIdx.x;

    if (bid < XBLOCKS) {
        // ---- X: 2 float4 per thread (8 fp32), gathered valid rows ----
        size_t t = (size_t)bid * 256 + tid;
        const size_t total = (size_t)M_DIM * (K_DIM / 8);
        if (t >= total) return;
        int d  = (int)(t / (K_DIM / 8));
        if (d >= g_Mvalid) return;
        int kk = (int)(t % (K_DIM / 8)) * 8;
        int src = g_rowsrc[d];
        const float* xp = X + (size_t)src * K_DIM + kk;
        float4 v0 = *(const float4*)(xp);
        float4 v1 = *(const float4*)(xp + 4);
        float f[8] = {v0.x, v0.y, v0.z, v0.w, v1.x, v1.y, v1.z, v1.w};
        uint32_t hi[4], lo[4];
        #pragma unroll
        for (int p = 0; p < 4; p++) {
            __nv_bfloat16 h0 = __float2bfloat16(f[2*p+0]);
            __nv_bfloat16 h1 = __float2bfloat16(f[2*p+1]);
            __nv_bfloat16 l0 = __float2bfloat16(f[2*p+0] - __bfloat162float(h0));
            __nv_bfloat16 l1 = __float2bfloat16(f[2*p+1] - __bfloat162float(h1));
            hi[p] = (uint32_t)__bfloat16_as_ushort(h0) | ((uint32_t)__bfloat16_as_ushort(h1) << 16);
            lo[p] = (uint32_t)__bfloat16_as_ushort(l0) | ((uint32_t)__bfloat16_as_ushort(l1) << 16);
        }
        size_t o = (size_t)d * K_PAD + kk;
        *(uint4*)(g_Xh + o) = make_uint4(hi[0], hi[1], hi[2], hi[3]);
        *(uint4*)(g_Xl + o) = make_uint4(lo[0], lo[1], lo[2], lo[3]);
    } else {
        // ---- W: transpose [K,N] -> [N,K_PAD] + split ----
        const int wb = bid - XBLOCKS;
        const int k0 = (wb % (K_PAD / 64)) * 64;
        const int n0 = (wb / (K_PAD / 64)) * 32;
        {
            int kr = tid >> 2;
            int nb = (tid & 3) * 8;
            int k = k0 + kr;
            if (k < K_DIM) {
                float4 a = *(const float4*)(W + (size_t)k * N_DIM + n0 + nb);
                float4 b = *(const float4*)(W + (size_t)k * N_DIM + n0 + nb + 4);
                s[kr][nb+0]=a.x; s[kr][nb+1]=a.y; s[kr][nb+2]=a.z; s[kr][nb+3]=a.w;
                s[kr][nb+4]=b.x; s[kr][nb+5]=b.y; s[kr][nb+6]=b.z; s[kr][nb+7]=b.w;
            } else {
                #pragma unroll
                for (int i = 0; i < 8; i++) s[kr][nb+i] = 0.0f;
            }
        }
        __syncthreads();
        {
            int nr = tid >> 3;
            int kb = (tid & 7) * 8;
            uint32_t hi[4], lo[4];
            #pragma unroll
            for (int p = 0; p < 4; p++) {
                float f0 = s[kb + 2*p + 0][nr];
                float f1 = s[kb + 2*p + 1][nr];
                __nv_bfloat16 h0 = __float2bfloat16(f0);
                __nv_bfloat16 h1 = __float2bfloat16(f1);
                __nv_bfloat16 l0 = __float2bfloat16(f0 - __bfloat162float(h0));
                __nv_bfloat16 l1 = __float2bfloat16(f1 - __bfloat162float(h1));
                hi[p] = (uint32_t)__bfloat16_as_ushort(h0) | ((uint32_t)__bfloat16_as_ushort(h1) << 16);
                lo[p] = (uint32_t)__bfloat16_as_ushort(l0) | ((uint32_t)__bfloat16_as_ushort(l1) << 16);
            }
            size_t o = (size_t)(n0 + nr) * K_PAD + k0 + kb;
            *(uint4*)(g_Wh + o) = make_uint4(hi[0], hi[1], hi[2], hi[3]);
            *(uint4*)(g_Wl + o) = make_uint4(lo[0], lo[1], lo[2], lo[3]);
        }
    }
}

// ---------------- Kernel: GEMM 128x128, warp 32x64, flat partition, frag double-buffer ----------------
__global__ void __launch_bounds__(256, 1)
gemm_kernel() {
    extern __shared__ char smem[];
    const uint32_t sb = smem_u32(smem);
    const int tid  = threadIdx.x;
    const int lane = tid & 31;
    const int wid  = tid >> 5;
    const int bid  = blockIdx.x;
    const int in   = bid & 7;
    const int slot = bid >> 3;
    const int bn   = in * GNT;

    const int mv     = g_Mvalid;
    const int tilesM = (mv + GMT - 1) / GMT;
    const int totalF = tilesM * NCHUNK;
    const int f0 = (slot * totalF) / NSLOT;
    const int f1 = ((slot + 1) * totalF) / NSLOT;

    const int m_off = (wid & 3) * 32;     // 4 warps down M
    const int n_off = (wid >> 2) * 64;    // 2 warps across N

    float acc[2][8][4];
    #pragma unroll
    for (int mi = 0; mi < 2; mi++)
        #pragma unroll
        for (int ni = 0; ni < 8; ni++)
            #pragma unroll
            for (int q = 0; q < 4; q++) acc[mi][ni][q] = 0.0f;

    const int aRow0 = m_off + (lane & 15);
    const int cA    = lane >> 4;
    const int bRow0 = n_off + ((lane & 16) >> 1) + (lane & 7);
    const int cB    = (lane >> 3) & 1;

    int im = f0 / NCHUNK;
    int j  = f0 - im * NCHUNK;

    fill_stage(sb + 0 * STAGE_BYTES, im, bn, j, tid);
    CP_COMMIT();
    if (f0 + 1 < f1) {
        int im1 = (f0 + 1) / NCHUNK;
        int j1  = (f0 + 1) - im1 * NCHUNK;
        fill_stage(sb + 1 * STAGE_BYTES, im1, bn, j1, tid);
    }
    CP_COMMIT();

    int seg = 0;
    for (int f = f0; f < f1; f++) {
        const int sidx = (f - f0) % STAGES;
        CP_WAIT1();
        __syncthreads();

        if (f + 2 < f1) {
            int imp = (f + 2) / NCHUNK;
            int jp  = (f + 2) - imp * NCHUNK;
            fill_stage(sb + ((f - f0 + 2) % STAGES) * STAGE_BYTES, imp, bn, jp, tid);
        }
        CP_COMMIT();

        const uint32_t st = sb + sidx * STAGE_BYTES;

        // double-buffered fragments across kk
        uint32_t ah[2][2][4], al[2][2][4], bh[2][4][4], bl[2][4][4];
        load_frags(st, 0, aRow0, cA, bRow0, cB, ah[0], al[0], bh[0], bl[0]);
        #pragma unroll
        for (int kk = 0; kk < 4; kk++) {
            const int cur = kk & 1;
            const int nxt = cur ^ 1;
            if (kk < 3)
                load_frags(st, kk + 1, aRow0, cA, bRow0, cB, ah[nxt], al[nxt], bh[nxt], bl[nxt]);
            #pragma unroll
            for (int mi = 0; mi < 2; mi++) {
                #pragma unroll
                for (int ni = 0; ni < 8; ni++) {
                    const uint32_t* fh = &bh[cur][ni >> 1][(ni & 1) * 2];
                    const uint32_t* fl = &bl[cur][ni >> 1][(ni & 1) * 2];
                    mma_bf16(acc[mi][ni], ah[cur][mi], fh);
                    mma_bf16(acc[mi][ni], ah[cur][mi], fl);
                    mma_bf16(acc[mi][ni], al[cur][mi], fh);
                }
            }
        }

        // advance / flush at m-tile boundary or range end
        j++;
        const bool bound = (j == NCHUNK);
        const bool last  = (f == f1 - 1);
        if (bound) j = 0;
        if (bound || last) {
            float* P = g_Part + ((size_t)bid * 2 + seg) * (GMT * GNT);
            #pragma unroll
            for (int mi = 0; mi < 2; mi++) {
                #pragma unroll
                for (int ni = 0; ni < 8; ni++) {
                    int r0 = m_off + mi * 16 + (lane >> 2);
                    int cc = n_off + ni * 8 + (lane & 3) * 2;
                    *(float2*)(P + r0 * GNT + cc) = make_float2(acc[mi][ni][0], acc[mi][ni][1]);
                    *(float2*)(P + (r0 + 8) * GNT + cc) = make_float2(acc[mi][ni][2], acc[mi][ni][3]);
                    #pragma unroll
                    for (int q = 0; q < 4; q++) acc[mi][ni][q] = 0.0f;
                }
            }
            seg++;
            if (bound) im++;
        }
    }
}

// ---------------- Kernel: gather partials + bias + ReLU + scatter (2 float4/thread) ----------------
__global__ __launch_bounds__(256)
void reduce_kernel(const float* __restrict__ bias) {
    // each thread: 2 adjacent float4 columns of one dense row
    const int idx = blockIdx.x * 256 + threadIdx.x;  // over [M_DIM, 128] pairs
    const int d   = idx >> 7;
    const int mv  = g_Mvalid;
    if (d >= mv) return;
    const int cp   = idx & 127;                      // pair index 0..127
    const int c    = cp * 2;                         // float4 col 0,2,..254
    const int im   = d >> 7;                         // m-tile (128 rows)
    const int rloc = d & 127;
    const int in   = c >> 5;                         // n-tile (32 f4 per 128 cols); pair stays in-tile
    const int lc   = (c & 31) * 4;

    const int tilesM = (mv + GMT - 1) / GMT;
    const int totalF = tilesM * NCHUNK;

    int sLo = (int)(((long)im * NCHUNK * NSLOT) / totalF) - 1;
    if (sLo < 0) sLo = 0;
    int sHi = (int)(((long)(im + 1) * NCHUNK * NSLOT) / totalF) + 2;
    if (sHi > NSLOT) sHi = NSLOT;

    float4 sum0 = *(const float4*)(bias + c * 4);
    float4 sum1 = *(const float4*)(bias + c * 4 + 4);
    #pragma unroll 1
    for (int slot = sLo; slot < sHi; slot++) {
        int f0   = (slot * totalF) / NSLOT;
        int f1   = ((slot + 1) * totalF) / NSLOT;
        int imLo = f0 / NCHUNK;
        int imHi = (f1 - 1) / NCHUNK;
        int seg = -1;
        if (im == imLo) seg = 0;
        else if (im == imHi) seg = 1;
        if (seg >= 0) {
            const float* P = g_Part + (((size_t)(slot * 8 + in)) * 2 + seg) * (GMT * GNT)
                           + rloc * GNT + lc;
            float4 v0 = *(const float4*)(P);
            float4 v1 = *(const float4*)(P + 4);
            sum0.x += v0.x; sum0.y += v0.y; sum0.z += v0.z; sum0.w += v0.w;
            sum1.x += v1.x; sum1.y += v1.y; sum1.z += v1.z; sum1.w += v1.w;
        }
    }
    float4 o0, o1;
    o0.x = fmaxf(sum0.x, 0.0f); o0.y = fmaxf(sum0.y, 0.0f);
    o0.z = fmaxf(sum0.z, 0.0f); o0.w = fmaxf(sum0.w, 0.0f);
    o1.x = fmaxf(sum1.x, 0.0f); o1.y = fmaxf(sum1.y, 0.0f);
    o1.z = fmaxf(sum1.z, 0.0f); o1.w = fmaxf(sum1.w, 0.0f);
    int row = g_rowsrc[d];
    float* hp = g_H + (size_t)row * N_DIM + c * 4;
    *(float4*)(hp)     = o0;
    *(float4*)(hp + 4) = o1;
}

// ---------------- Kernel: merged head (y==0: pool+activities, y>=1: actions row y-1) ----------------
__global__ __launch_bounds__(256)
void head_kernel(const float* __restrict__ w_act,
                 const float* __restrict__ b_act,
                 const float* __restrict__ w_acty,
                 const float* __restrict__ b_acty,
                 const int*   __restrict__ bboxes_num,
                 float* __restrict__ out) {
    const int bt   = blockIdx.x;
    const int mode = blockIdx.y;
    const int tid  = threadIdx.x;
    const int lane = tid & 31;
    const int warp = tid >> 5;

    int nvalid = bboxes_num[bt];
    nvalid = nvalid < 1 ? 1 : (nvalid > MAXN ? MAXN : nvalid);

    if (mode == 0) {
        const float4* h4 = (const float4*)(g_H + (size_t)bt * MAXN * N_DIM);
        __shared__ float pooled[N_DIM];
        {
            float4 m = h4[tid];
            #pragma unroll
            for (int n = 1; n < MAXN; n++) {
                if (n < nvalid) {
                    float4 v = h4[n * 256 + tid];
                    m.x = fmaxf(m.x, v.x); m.y = fmaxf(m.y, v.y);
                    m.z = fmaxf(m.z, v.z); m.w = fmaxf(m.w, v.w);
                }
            }
            ((float4*)pooled)[tid] = m;
        }
        __syncthreads();
        for (int g = warp; g < G_DIM; g += 8) {
            float s = 0.0f;
            for (int i = lane; i < 256; i += 32) {
                float4 pv = ((const float4*)pooled)[i];
                int f = i * 4;
                s = fmaf(pv.x, w_acty[(f + 0) * G_DIM + g], s);
                s = fmaf(pv.y, w_acty[(f + 1) * G_DIM + g], s);
                s = fmaf(pv.z, w_acty[(f + 2) * G_DIM + g], s);
                s = fmaf(pv.w, w_acty[(f + 3) * G_DIM + g], s);
            }
            #pragma unroll
            for (int o = 16; o; o >>= 1) s += __shfl_xor_sync(0xFFFFFFFFu, s, o);
            if (lane == 0)
                out[BT * MAXN * A_DIM + bt * G_DIM + g] = s + b_acty[g];
        }
    } else {
        const int n = mode - 1;
        if (warp >= A_DIM) return;
        const int a = warp;
        if (n >= nvalid) {
            if (lane == 0) out[(bt * MAXN + n) * A_DIM + a] = 0.0f;
            return;
        }
        const float4* hr = (const float4*)(g_H + ((size_t)bt * MAXN + n) * N_DIM);
        float s = 0.0f;
        #pragma unroll
        for (int r = 0; r < 8; r++) {
            int i = lane + r * 32;
            float4 hv = hr[i];
            int f = i * 4;
            s = fmaf(hv.x, w_act[(f + 0) * A_DIM + a], s);
            s = fmaf(hv.y, w_act[(f + 1) * A_DIM + a], s);
            s = fmaf(hv.z, w_act[(f + 2) * A_DIM + a], s);
            s = fmaf(hv.w, w_act[(f + 3) * A_DIM + a], s);
        }
        #pragma unroll
        for (int o = 16; o; o >>= 1) s += __shfl_xor_sync(0xFFFFFFFFu, s, o);
        if (lane == 0) out[(bt * MAXN + n) * A_DIM + a] = s + b_act[a];
    }
}

// ---------------- launch ----------------
extern "C" void kernel_launch(void* const* d_in, const int* in_sizes, int n_in,
                              void* d_out, int out_size) {
    const float* X      = (const float*)d_in[0];
    const float* w_emb  = (const float*)d_in[1];
    const float* b_emb  = (const float*)d_in[2];
    const float* w_act  = (const float*)d_in[3];
    const float* b_act  = (const float*)d_in[4];
    const float* w_acty = (const float*)d_in[5];
    const float* b_acty = (const float*)d_in[6];
    const int*   bboxes = (const int*)d_in[7];
    float* out = (float*)d_out;

    cudaFuncSetAttribute(gemm_kernel, cudaFuncAttributeMaxDynamicSharedMemorySize, SMEM_TOTAL);

    prefix_kernel<<<1, 128>>>(bboxes);
    convert_kernel<<<XBLOCKS + WBLOCKS, 256>>>(X, w_emb);
    gemm_kernel<<<8 * NSLOT, 256, SMEM_TOTAL>>>();       // 144 CTAs, flat-balanced
    {
        int blocks = (M_DIM * 128 + 255) / 256;          // 2 float4 per thread
        reduce_kernel<<<blocks, 256>>>(b_emb);
    }
    {
        dim3 g(BT, MAXN + 1);
        head_kernel<<<g, 256>>>(w_act, b_act, w_acty, b_acty, bboxes, out);
    }
}